// round 10
// baseline (speedup 1.0000x reference)
#include <cuda_runtime.h>
#include <math.h>

#define K        8
#define D        256
#define C4       (D / 4)     // 64 float4 columns
#define TILE_N   64          // output rows per block
#define ROWS_T   (TILE_N + K - 1)   // 71 rows staged in SMEM
#define THREADS  256         // 64 cols x 4 groups
#define RPT      16          // output rows per thread
#define NEGV     (-1e9f)

#define SMEM_TILE_BYTES  (ROWS_T * D * 4)            // 72704
#define SMEM_ALPHA_OFF   SMEM_TILE_BYTES
#define SMEM_ALPHA_BYTES (TILE_N * K * 4)            // 2048
#define SMEM_MBAR_OFF    (SMEM_ALPHA_OFF + SMEM_ALPHA_BYTES)
#define SMEM_TOTAL       (SMEM_MBAR_OFF + 16)

typedef unsigned long long u64;

__device__ __forceinline__ void fma2(u64& acc, u64 v, u64 a) {
    asm("fma.rn.f32x2 %0, %1, %2, %3;" : "=l"(acc) : "l"(v), "l"(a), "l"(acc));
}
__device__ __forceinline__ u64 pack2(float a) {
    u64 d;
    asm("mov.b64 %0, {%1, %1};" : "=l"(d) : "f"(a));
    return d;
}
__device__ __forceinline__ unsigned smem_u32(const void* p) {
    unsigned a;
    asm("{ .reg .u64 t; cvta.to.shared.u64 t, %1; cvt.u32.u64 %0, t; }"
        : "=r"(a) : "l"(p));
    return a;
}

// valid_mask may arrive as int32 / uint8(bool) / float32; detect from word 0
// (guaranteed "true" since lengths >= N/2).
__device__ __forceinline__ bool mask_at(const void* m, int fmt, long i) {
    if (fmt == 1) return ((const unsigned char*)m)[i] != 0;
    if (fmt == 2) return ((const float*)m)[i] != 0.0f;
    return ((const int*)m)[i] != 0;
}

__global__ __launch_bounds__(THREADS)
void mixer_kernel(const float* __restrict__ x,
                  const float* __restrict__ dts,
                  const void*  __restrict__ maskp,
                  const float* __restrict__ w,
                  const float* __restrict__ beta,
                  float* __restrict__ out,
                  int N)
{
    extern __shared__ char smem[];
    float* s_tile  = (float*)smem;                        // [ROWS_T][256]
    float* s_alpha = (float*)(smem + SMEM_ALPHA_OFF);     // [TILE_N][8]
    const unsigned mbar = smem_u32(smem + SMEM_MBAR_OFF);

    const int  b    = blockIdx.y;
    const int  n0   = blockIdx.x * TILE_N;
    const int  tid  = threadIdx.x;
    const long base = (long)b * N;

    // ---- 1) init mbarrier, then launch ONE bulk copy of the whole tile ----
    if (tid == 0) {
        asm volatile("mbarrier.init.shared.b64 [%0], 1;" :: "r"(mbar) : "memory");
    }
    __syncthreads();   // init visible before complete_tx can land

    const int rows = (N - n0 < ROWS_T) ? (N - n0) : ROWS_T;
    const unsigned bytes = (unsigned)rows * D * 4u;
    if (tid == 0) {
        asm volatile("mbarrier.arrive.expect_tx.shared.b64 _, [%0], %1;"
                     :: "r"(mbar), "r"(bytes) : "memory");
        asm volatile(
            "cp.async.bulk.shared::cta.global.mbarrier::complete_tx::bytes "
            "[%0], [%1], %2, [%3];"
            :: "r"(smem_u32(s_tile)), "l"(x + (base + n0) * (long)D),
               "r"(bytes), "r"(mbar) : "memory");
    }

    // ---- 2) zero-fill pad rows (only last tile per batch) — overlaps copy --
    if (rows < ROWS_T) {
        float4* pad = (float4*)(s_tile + rows * D);
        const int npad4 = (ROWS_T - rows) * C4;
        for (int i = tid; i < npad4; i += THREADS)
            pad[i] = make_float4(0.f, 0.f, 0.f, 0.f);
    }

    // ---- mask format detection (uniform) ----
    const unsigned int w0 = *((const unsigned int*)maskp);
    int fmt = 0;
    if (w0 == 0x01010101u)      fmt = 1;   // uint8 bool
    else if (w0 == 0x3F800000u) fmt = 2;   // float32

    // ---- 3) Phase 1: alpha[TILE_N][K] — overlaps the bulk copy ----
    if (tid < TILE_N) {
        const int  n      = n0 + tid;
        const bool valid0 = mask_at(maskp, fmt, base + n);
        const float dt0   = dts[base + n];

        float score[K];
        bool  cv[K];
        cv[0]    = valid0;
        score[0] = valid0 ? 0.0f : NEGV;
        #pragma unroll
        for (int p = 1; p < K; p++) {
            const int np = n + p;
            bool  c  = false;
            float td = 0.0f;
            if (np < N) {
                c = valid0 && mask_at(maskp, fmt, base + np);
                if (c) td = fmaxf(dts[base + np] - dt0, 0.0f);
            }
            cv[p]    = c;
            score[p] = c ? -td : NEGV;
        }

        float m = score[0];
        #pragma unroll
        for (int p = 1; p < K; p++) m = fmaxf(m, score[p]);
        float e[K], es = 0.0f;
        #pragma unroll
        for (int p = 0; p < K; p++) { e[p] = __expf(score[p] - m); es += e[p]; }
        const float inv_es = 1.0f / es;

        float wv[K];
        #pragma unroll
        for (int p = 0; p < K; p++) wv[p] = w[p];
        float wm = wv[0];
        #pragma unroll
        for (int p = 1; p < K; p++) wm = fmaxf(wm, wv[p]);
        float we[K], ws = 0.0f;
        #pragma unroll
        for (int p = 0; p < K; p++) { we[p] = __expf(wv[p] - wm); ws += we[p]; }
        const float inv_ws = 1.0f / ws;
        const float bsig   = 1.0f / (1.0f + __expf(-beta[0]));
        const float omb    = 1.0f - bsig;

        float a[K], asum = 0.0f;
        #pragma unroll
        for (int p = 0; p < K; p++) {
            a[p] = cv[p] ? (bsig * we[p] * inv_ws + omb * e[p] * inv_es) : 0.0f;
            asum += a[p];
        }
        const float inv = 1.0f / fmaxf(asum, 1e-8f);
        #pragma unroll
        for (int p = 0; p < K; p++) s_alpha[tid * K + p] = a[p] * inv;
    }
    __syncthreads();   // s_alpha + pad rows ready

    // ---- 4) wait for the bulk copy ----
    {
        unsigned done;
        asm volatile(
            "{\n\t .reg .pred p;\n\t"
            "mbarrier.try_wait.parity.acquire.cta.shared::cta.b64 p, [%1], 0;\n\t"
            "selp.b32 %0, 1, 0, p;\n\t}"
            : "=r"(done) : "r"(mbar) : "memory");
        if (!done) {
            asm volatile(
                "{\n\t .reg .pred P1;\n\t"
                "WL_%=:\n\t"
                "mbarrier.try_wait.parity.acquire.cta.shared::cta.b64 P1, [%0], 0, 0x989680;\n\t"
                "@P1 bra.uni WD_%=;\n\t"
                "bra.uni WL_%=;\n\t"
                "WD_%=:\n\t}"
                :: "r"(mbar) : "memory");
        }
    }

    // ---- 5) compute: sliding 8-row register window over SMEM ----
    const int c4 = tid & (C4 - 1);   // 0..63
    const int g  = tid >> 6;         // 0..3
    const int r0 = g * RPT;

    const ulonglong2* __restrict__ tr =
        (const ulonglong2*)s_tile + r0 * (long)C4 + c4;
    ulonglong2* __restrict__ orow =
        (ulonglong2*)out + (base + n0 + r0) * (long)C4 + c4;

    ulonglong2 win[K];
    #pragma unroll
    for (int j = 0; j < K; j++) win[j] = tr[j * C4];

    #pragma unroll
    for (int r = 0; r < RPT; r++) {
        const float4* ar = (const float4*)&s_alpha[(r0 + r) * K];
        const float4 a0 = ar[0];
        const float4 a1 = ar[1];
        const float  al[K] = {a0.x, a0.y, a0.z, a0.w, a1.x, a1.y, a1.z, a1.w};

        u64 accx = 0ULL, accy = 0ULL;
        #pragma unroll
        for (int p = 0; p < K; p++) {
            const ulonglong2 v = win[(r + p) & (K - 1)];
            const u64 ap = pack2(al[p]);
            fma2(accx, v.x, ap);
            fma2(accy, v.y, ap);
        }
        orow[(long)r * C4] = make_ulonglong2(accx, accy);

        if (r < RPT - 1)
            win[r & (K - 1)] = tr[(r + K) * C4];
    }
}

extern "C" void kernel_launch(void* const* d_in, const int* in_sizes, int n_in,
                              void* d_out, int out_size)
{
    const float* x    = (const float*)d_in[0];
    const float* dts  = (const float*)d_in[1];
    const void*  mask = d_in[2];
    const float* w    = (const float*)d_in[3];
    const float* beta = (const float*)d_in[4];

    const int BN = in_sizes[1];   // B * N
    const int B  = 8;
    const int N  = BN / B;        // 4096

    cudaFuncSetAttribute(mixer_kernel,
                         cudaFuncAttributeMaxDynamicSharedMemorySize, SMEM_TOTAL);

    dim3 grid(N / TILE_N, B);
    mixer_kernel<<<grid, THREADS, SMEM_TOTAL>>>(x, dts, mask, w, beta,
                                                (float*)d_out, N);
}

// round 11
// speedup vs baseline: 1.0266x; 1.0266x over previous
#include <cuda_runtime.h>
#include <math.h>

#define K        8
#define C4       64          // 16-byte columns per row (d=256 floats)
#define TILE_N   32          // output rows per block
#define RPT      16          // rows per thread
#define THREADS  128         // 64 cols x 2 groups
#define WIN      12          // register ring (8-row window + 4 prefetch)
#define MAXROW   (RPT + K - 2)   // last row ever tapped (22)
#define NEGV     (-1e9f)

typedef unsigned long long u64;

// packed fp32x2 FMA (FFMA2 path, only reachable via PTX)
__device__ __forceinline__ void fma2(u64& acc, u64 v, u64 a) {
    asm("fma.rn.f32x2 %0, %1, %2, %3;" : "=l"(acc) : "l"(v), "l"(a), "l"(acc));
}
__device__ __forceinline__ u64 pack2(float a) {
    u64 d;
    asm("mov.b64 %0, {%1, %1};" : "=l"(d) : "f"(a));
    return d;
}

// valid_mask may arrive as int32 / uint8(bool) / float32; detect from word 0
// (guaranteed "true" since lengths >= N/2).
__device__ __forceinline__ bool mask_at(const void* m, int fmt, long i) {
    if (fmt == 1) return ((const unsigned char*)m)[i] != 0;
    if (fmt == 2) return ((const float*)m)[i] != 0.0f;
    return ((const int*)m)[i] != 0;
}

__global__ __launch_bounds__(THREADS)
void mixer_kernel(const float* __restrict__ x,
                  const float* __restrict__ dts,
                  const void*  __restrict__ maskp,
                  const float* __restrict__ w,
                  const float* __restrict__ beta,
                  float* __restrict__ out,
                  int N)
{
    // alphas pre-duplicated as {a,a} u64 -> inner loop needs no packing MOVs
    __shared__ u64 s_alpha2[TILE_N * K];

    const int  b    = blockIdx.y;
    const int  n0   = blockIdx.x * TILE_N;
    const int  tid  = threadIdx.x;
    const long base = (long)b * N;

    // ---- per-thread column/row-strip mapping (phase 2) ----
    const int c4     = tid & (C4 - 1);   // 0..63
    const int g      = tid >> 6;         // 0..1
    const int r0     = g * RPT;
    const int nstart = n0 + r0;

    const ulonglong2* __restrict__ xr =
        (const ulonglong2*)x + (base + nstart) * (long)C4 + c4;
    ulonglong2* __restrict__ orow =
        (ulonglong2*)out + (base + nstart) * (long)C4 + c4;

    // ---- issue pipeline-init loads FIRST (12 independent LDG.128) ----
    ulonglong2 buf[WIN];
    #pragma unroll
    for (int j = 0; j < WIN; j++) {
        const int nr = nstart + j;
        buf[j] = (nr < N) ? xr[(long)j * C4] : make_ulonglong2(0ULL, 0ULL);
    }

    // ---- mask format detection (uniform) ----
    const unsigned int w0 = *((const unsigned int*)maskp);
    int fmt = 0;
    if (w0 == 0x01010101u)      fmt = 1;   // uint8 bool
    else if (w0 == 0x3F800000u) fmt = 2;   // float32

    // ================= Phase 1: alpha[TILE_N][K] (overlaps window loads) ====
    if (tid < TILE_N) {
        const int  n      = n0 + tid;
        const bool valid0 = mask_at(maskp, fmt, base + n);
        const float dt0   = dts[base + n];

        float score[K];
        bool  cv[K];
        cv[0]    = valid0;
        score[0] = valid0 ? 0.0f : NEGV;
        #pragma unroll
        for (int p = 1; p < K; p++) {
            const int np = n + p;
            bool  c  = false;
            float td = 0.0f;
            if (np < N) {
                c = valid0 && mask_at(maskp, fmt, base + np);
                if (c) td = fmaxf(dts[base + np] - dt0, 0.0f);
            }
            cv[p]    = c;
            score[p] = c ? -td : NEGV;
        }

        float m = score[0];
        #pragma unroll
        for (int p = 1; p < K; p++) m = fmaxf(m, score[p]);
        float e[K], es = 0.0f;
        #pragma unroll
        for (int p = 0; p < K; p++) { e[p] = __expf(score[p] - m); es += e[p]; }
        const float inv_es = 1.0f / es;

        float wv[K];
        #pragma unroll
        for (int p = 0; p < K; p++) wv[p] = w[p];
        float wm = wv[0];
        #pragma unroll
        for (int p = 1; p < K; p++) wm = fmaxf(wm, wv[p]);
        float we[K], ws = 0.0f;
        #pragma unroll
        for (int p = 0; p < K; p++) { we[p] = __expf(wv[p] - wm); ws += we[p]; }
        const float inv_ws = 1.0f / ws;
        const float bsig   = 1.0f / (1.0f + __expf(-beta[0]));
        const float omb    = 1.0f - bsig;

        float a[K], asum = 0.0f;
        #pragma unroll
        for (int p = 0; p < K; p++) {
            a[p] = cv[p] ? (bsig * we[p] * inv_ws + omb * e[p] * inv_es) : 0.0f;
            asum += a[p];
        }
        const float inv = 1.0f / fmaxf(asum, 1e-8f);
        #pragma unroll
        for (int p = 0; p < K; p++) s_alpha2[tid * K + p] = pack2(a[p] * inv);
    }
    __syncthreads();

    // ========== Phase 2: pipelined sliding window (R4/R8 pattern) ==========
    // Consume slot r%WIN first, THEN load row r+WIN directly into that slot
    // (no temp -> no completion wait; WAR on the slot is free). Row r+WIN is
    // first consumed at iter r+WIN-K+1 (distance 5). Dead prefetches skipped
    // at compile time.
    #pragma unroll
    for (int r = 0; r < RPT; r++) {
        // 8 pre-packed alphas: 4x LDS.128 broadcast
        const ulonglong2* ar = (const ulonglong2*)&s_alpha2[(r0 + r) * K];
        const ulonglong2 q0 = ar[0], q1 = ar[1], q2 = ar[2], q3 = ar[3];
        const u64 ap[K] = {q0.x, q0.y, q1.x, q1.y, q2.x, q2.y, q3.x, q3.y};

        u64 accx = 0ULL, accy = 0ULL;
        #pragma unroll
        for (int p = 0; p < K; p++) {
            const ulonglong2 v = buf[(r + p) % WIN];
            fma2(accx, v.x, ap[p]);
            fma2(accy, v.y, ap[p]);
        }
        // streaming store: out is never re-read -> don't pollute L2
        __stcs((ulonglong2*)(orow + (long)r * C4), make_ulonglong2(accx, accy));

        if (r + WIN <= MAXROW) {           // compile-time: only useful rows
            const int nr = nstart + r + WIN;
            buf[r % WIN] =
                (nr < N) ? xr[(long)(r + WIN) * C4] : make_ulonglong2(0ULL, 0ULL);
        }
    }
}

extern "C" void kernel_launch(void* const* d_in, const int* in_sizes, int n_in,
                              void* d_out, int out_size)
{
    const float* x    = (const float*)d_in[0];
    const float* dts  = (const float*)d_in[1];
    const void*  mask = d_in[2];
    const float* w    = (const float*)d_in[3];
    const float* beta = (const float*)d_in[4];

    const int BN = in_sizes[1];   // B * N
    const int B  = 8;
    const int N  = BN / B;        // 4096

    dim3 grid(N / TILE_N, B);
    mixer_kernel<<<grid, THREADS>>>(x, dts, mask, w, beta, (float*)d_out, N);
}